// round 4
// baseline (speedup 1.0000x reference)
#include <cuda_runtime.h>
#include <cuda_fp16.h>
#include <cuda_bf16.h>
#include <cstdint>

#define BSZ 8192
#define DIM 256

// ---------------- device globals (scratch; no runtime allocation) ----------------
__device__ uint8_t        g_K8[(size_t)BSZ * BSZ];         // 67 MB: K = exp(G-1) as e4m3
__device__ __nv_bfloat16  g_imgb[BSZ * DIM];
__device__ __nv_bfloat16  g_txtb[BSZ * DIM];
__device__ float g_vimg[BSZ], g_vtxt[BSZ], g_uimg[BSZ], g_utxt[BSZ];
__device__ float g_rA[BSZ], g_cA[BSZ], g_rB[BSZ], g_cB[BSZ];
__device__ float g_part[BSZ];

// ---------------- fp8 helpers ----------------
__device__ __forceinline__ __half2 cvt8x2(uint32_t w) {   // low 16 bits = 2 e4m3 -> half2
    uint32_t r;
    asm("cvt.rn.f16x2.e4m3x2 %0, %1;" : "=r"(r) : "h"((unsigned short)w));
    return *reinterpret_cast<__half2*>(&r);
}
__device__ __forceinline__ unsigned short pack_e4m3(float hi, float lo) {
    unsigned short r;  // d[7:0]=cvt(lo), d[15:8]=cvt(hi)
    asm("cvt.rn.satfinite.e4m3x2.f32 %0, %1, %2;" : "=h"(r) : "f"(hi), "f"(lo));
    return r;
}
__device__ __forceinline__ float k8_to_f(uint8_t b) {
    uint32_t r;
    asm("cvt.rn.f16x2.e4m3x2 %0, %1;" : "=r"(r) : "h"((unsigned short)b));
    return __low2float(*reinterpret_cast<__half2*>(&r));
}

// ---------------- fp32 -> bf16 convert ----------------
__global__ void cvt_kernel(const float* __restrict__ img, const float* __restrict__ txt) {
    int i = blockIdx.x * blockDim.x + threadIdx.x;
    if (i < BSZ * DIM) {
        g_imgb[i] = __float2bfloat16_rn(img[i]);
        g_txtb[i] = __float2bfloat16_rn(txt[i]);
    }
}

// ================= GEMM: K = exp(img @ txt^T - 1), store e4m3 =================
#define SP 264
#define NB 64
#define STRIPC 1024
#define NTILES (STRIPC / NB)
#define GEMM_SMEM_BYTES ((128 * SP + 2 * NB * SP) * 2)

__device__ __forceinline__ void mma_bf16(float c[4], const uint32_t a[4], const uint32_t b[2]) {
    asm volatile(
        "mma.sync.aligned.m16n8k16.row.col.f32.bf16.bf16.f32 "
        "{%0,%1,%2,%3}, {%4,%5,%6,%7}, {%8,%9}, {%0,%1,%2,%3};\n"
        : "+f"(c[0]), "+f"(c[1]), "+f"(c[2]), "+f"(c[3])
        : "r"(a[0]), "r"(a[1]), "r"(a[2]), "r"(a[3]), "r"(b[0]), "r"(b[1]));
}
__device__ __forceinline__ void cp_async16(void* smem_dst, const void* gsrc) {
    uint32_t sa = (uint32_t)__cvta_generic_to_shared(smem_dst);
    asm volatile("cp.async.cg.shared.global [%0], [%1], 16;\n" :: "r"(sa), "l"(gsrc));
}

__global__ __launch_bounds__(256, 1) void gemm_exp_kernel() {
    extern __shared__ __nv_bfloat16 sm[];
    __nv_bfloat16* As = sm;
    __nv_bfloat16* Bs = sm + 128 * SP;

    const int tid  = threadIdx.x;
    const int lane = tid & 31, warp = tid >> 5;
    const int g = lane >> 2, tq = lane & 3;
    const int wm = warp & 3, wn = warp >> 2;

    const int mTile  = blockIdx.y * 128;
    const int strip0 = blockIdx.x * STRIPC;

    for (int idx = tid; idx < 128 * 32; idx += 256) {
        int r = idx >> 5, c8 = idx & 31;
        *reinterpret_cast<float4*>(As + r * SP + c8 * 8) =
            *reinterpret_cast<const float4*>(g_imgb + (size_t)(mTile + r) * DIM + c8 * 8);
    }
    {
        for (int idx = tid; idx < NB * 32; idx += 256) {
            int r = idx >> 5, c8 = idx & 31;
            cp_async16(Bs + r * SP + c8 * 8, g_txtb + (size_t)(strip0 + r) * DIM + c8 * 8);
        }
        asm volatile("cp.async.commit_group;\n");
    }

    for (int bt = 0; bt < NTILES; bt++) {
        if (bt + 1 < NTILES) {
            __nv_bfloat16* Bd = Bs + ((bt + 1) & 1) * NB * SP;
            const int nb0 = strip0 + (bt + 1) * NB;
            for (int idx = tid; idx < NB * 32; idx += 256) {
                int r = idx >> 5, c8 = idx & 31;
                cp_async16(Bd + r * SP + c8 * 8, g_txtb + (size_t)(nb0 + r) * DIM + c8 * 8);
            }
            asm volatile("cp.async.commit_group;\n");
            asm volatile("cp.async.wait_group 1;\n");
        } else {
            asm volatile("cp.async.wait_group 0;\n");
        }
        __syncthreads();

        const __nv_bfloat16* Bb = Bs + (bt & 1) * NB * SP;
        float c[2][4][4];
        #pragma unroll
        for (int mi = 0; mi < 2; mi++)
            #pragma unroll
            for (int ni = 0; ni < 4; ni++)
                #pragma unroll
                for (int k = 0; k < 4; k++) c[mi][ni][k] = 0.0f;

        #pragma unroll
        for (int ks = 0; ks < 16; ks++) {
            const int k0 = ks * 16;
            uint32_t a[2][4], b[4][2];
            #pragma unroll
            for (int mi = 0; mi < 2; mi++) {
                int rb = wm * 32 + mi * 16;
                a[mi][0] = *reinterpret_cast<const uint32_t*>(As + (rb + g)     * SP + k0 + 2 * tq);
                a[mi][1] = *reinterpret_cast<const uint32_t*>(As + (rb + g + 8) * SP + k0 + 2 * tq);
                a[mi][2] = *reinterpret_cast<const uint32_t*>(As + (rb + g)     * SP + k0 + 2 * tq + 8);
                a[mi][3] = *reinterpret_cast<const uint32_t*>(As + (rb + g + 8) * SP + k0 + 2 * tq + 8);
            }
            #pragma unroll
            for (int ni = 0; ni < 4; ni++) {
                int nb = wn * 32 + ni * 8;
                b[ni][0] = *reinterpret_cast<const uint32_t*>(Bb + (nb + g) * SP + k0 + 2 * tq);
                b[ni][1] = *reinterpret_cast<const uint32_t*>(Bb + (nb + g) * SP + k0 + 2 * tq + 8);
            }
            #pragma unroll
            for (int mi = 0; mi < 2; mi++)
                #pragma unroll
                for (int ni = 0; ni < 4; ni++)
                    mma_bf16(c[mi][ni], a[mi], b[ni]);
        }

        const int nTile = strip0 + bt * NB;
        #pragma unroll
        for (int mi = 0; mi < 2; mi++) {
            #pragma unroll
            for (int ni = 0; ni < 4; ni++) {
                int row0 = mTile + wm * 32 + mi * 16 + g;
                int col  = nTile + wn * 32 + ni * 8 + 2 * tq;
                unsigned short p01 = pack_e4m3(__expf(c[mi][ni][1] - 1.0f), __expf(c[mi][ni][0] - 1.0f));
                unsigned short p23 = pack_e4m3(__expf(c[mi][ni][3] - 1.0f), __expf(c[mi][ni][2] - 1.0f));
                *reinterpret_cast<unsigned short*>(g_K8 + (size_t)row0 * BSZ + col)       = p01;
                *reinterpret_cast<unsigned short*>(g_K8 + (size_t)(row0 + 8) * BSZ + col) = p23;
            }
        }
        __syncthreads();
    }
}

// ---------------- init ----------------
__global__ void init_kernel() {
    int i = blockIdx.x * blockDim.x + threadIdx.x;
    if (i < BSZ) { g_vimg[i] = 1.0f; g_vtxt[i] = 1.0f; g_rA[i] = 0.0f; g_cA[i] = 0.0f; }
}

// ============== dual matvec pass: y1 += K x1 (rows), y2 += K^T x2 (cols) ==============
// Thread owns 16 cols (one LDG.128 of fp8 per row). 4-row steps, double-buffered.
#define PR 32

__device__ __forceinline__ float reduce4rows(const float a[4], int lane) {
    float b0, b1;
    {
        bool o = (lane & 1) != 0;
        float s0 = o ? a[0] : a[1];
        float r0 = __shfl_xor_sync(0xffffffffu, s0, 1);
        b0 = (o ? a[1] : a[0]) + r0;
        float s1 = o ? a[2] : a[3];
        float r1 = __shfl_xor_sync(0xffffffffu, s1, 1);
        b1 = (o ? a[3] : a[2]) + r1;
    }
    float c;
    {
        bool o = (lane & 2) != 0;
        float s = o ? b0 : b1;
        float r = __shfl_xor_sync(0xffffffffu, s, 2);
        c = (o ? b1 : b0) + r;
    }
    c += __shfl_xor_sync(0xffffffffu, c, 4);
    c += __shfl_xor_sync(0xffffffffu, c, 8);
    c += __shfl_xor_sync(0xffffffffu, c, 16);
    return c;   // every lane holds full warp sum for row (lane & 3)
}

__device__ __forceinline__ void do4rows(const uint4 q[4], int rb,
                                        const float* sx2, const __half2* v2,
                                        __half2* cp2, float srow[PR][9],
                                        int lane, int warp) {
    float acc[4];
    #pragma unroll
    for (int rr = 0; rr < 4; rr++) {
        __half2 x2h = __float2half2_rn(sx2[rb + rr]);
        const uint32_t* w = reinterpret_cast<const uint32_t*>(&q[rr]);
        __half2 a2 = __float2half2_rn(0.0f);
        #pragma unroll
        for (int j = 0; j < 4; j++) {
            __half2 k0 = cvt8x2(w[j]);
            __half2 k1 = cvt8x2(w[j] >> 16);
            a2 = __hfma2(k0, v2[2 * j],     a2);
            a2 = __hfma2(k1, v2[2 * j + 1], a2);
            cp2[2 * j]     = __hfma2(k0, x2h, cp2[2 * j]);
            cp2[2 * j + 1] = __hfma2(k1, x2h, cp2[2 * j + 1]);
        }
        acc[rr] = __low2float(a2) + __high2float(a2);
    }
    float d = reduce4rows(acc, lane);
    if (lane < 4) srow[rb + lane][warp] = d;
}

__global__ __launch_bounds__(256) void pass_dual(int mode) {
    const float *x1, *x2; float *y1, *y2;
    if (mode == 0) { x1 = g_vimg; x2 = g_vtxt; y1 = g_rA; y2 = g_cA; }
    else           { x1 = g_utxt; x2 = g_uimg; y1 = g_rB; y2 = g_cB; }

    const int t = threadIdx.x, lane = t & 31, warp = t >> 5;
    const int c  = blockIdx.x * 4096 + t * 16;
    const int r0 = blockIdx.y * PR;

    __half2 v2[8];
    #pragma unroll
    for (int j = 0; j < 8; j++)
        v2[j] = __floats2half2_rn(x1[c + 2 * j], x1[c + 2 * j + 1]);
    __half2 cp2[8];
    #pragma unroll
    for (int j = 0; j < 8; j++) cp2[j] = __float2half2_rn(0.0f);

    __shared__ float sx2[PR];
    __shared__ float srow[PR][9];
    if (t < PR) sx2[t] = x2[r0 + t];
    __syncthreads();

    const uint8_t* Kb = g_K8 + (size_t)r0 * BSZ + c;

    uint4 qA[4], qB[4];
    #pragma unroll
    for (int rr = 0; rr < 4; rr++)
        qA[rr] = *reinterpret_cast<const uint4*>(Kb + (size_t)rr * BSZ);

    #pragma unroll
    for (int itb = 0; itb < PR / 8; itb++) {
        const int sA = itb * 8, sB = itb * 8 + 4;
        #pragma unroll
        for (int rr = 0; rr < 4; rr++)
            qB[rr] = *reinterpret_cast<const uint4*>(Kb + (size_t)(sB + rr) * BSZ);
        do4rows(qA, sA, sx2, v2, cp2, srow, lane, warp);
        if (itb + 1 < PR / 8) {
            #pragma unroll
            for (int rr = 0; rr < 4; rr++)
                qA[rr] = *reinterpret_cast<const uint4*>(Kb + (size_t)(sA + 8 + rr) * BSZ);
        }
        do4rows(qB, sB, sx2, v2, cp2, srow, lane, warp);
    }
    __syncthreads();

    if (t < PR) {
        float s = 0.0f;
        #pragma unroll
        for (int w = 0; w < 8; w++) s += srow[t][w];
        atomicAdd(&y1[r0 + t], s);
    }
    #pragma unroll
    for (int j = 0; j < 8; j++) {
        float2 f = __half22float2(cp2[j]);
        atomicAdd(&y2[c + 2 * j],     f.x);
        atomicAdd(&y2[c + 2 * j + 1], f.y);
    }
}

// ---------------- scalar update kernels ----------------
__global__ void upd_u_kernel() {
    int i = blockIdx.x * blockDim.x + threadIdx.x;
    if (i < BSZ) {
        g_uimg[i] = 1.0f / g_rA[i];
        g_utxt[i] = 1.0f / g_cA[i];
        g_rB[i] = 0.0f; g_cB[i] = 0.0f;
    }
}

__global__ void upd_v_kernel() {
    int i = blockIdx.x * blockDim.x + threadIdx.x;
    if (i < BSZ) {
        float tt = g_vimg[i] * g_cB[i];
        float f1 = fmaxf(0.5f / tt, 1.0f);
        tt *= f1;
        float f2 = fminf(4.5f / tt, 1.0f);
        g_vimg[i] *= f1 * f2;

        float tu = g_vtxt[i] * g_rB[i];
        float h1 = fmaxf(0.5f / tu, 1.0f);
        tu *= h1;
        float h2 = fminf(4.5f / tu, 1.0f);
        g_vtxt[i] *= h1 * h2;

        g_rA[i] = 0.0f; g_cA[i] = 0.0f;
    }
}

// ---------------- finalize ----------------
__global__ void finalize1_kernel(const int* __restrict__ labels) {
    int i = blockIdx.x * blockDim.x + threadIdx.x;
    if (i < BSZ) {
        int l = labels[i];
        float p1 = g_uimg[i] * k8_to_f(g_K8[(size_t)i * BSZ + l]) * g_vimg[l];
        float p2 = g_utxt[i] * k8_to_f(g_K8[(size_t)l * BSZ + i]) * g_vtxt[l];
        float S1 = (float)BSZ + g_uimg[i] * g_rA[i];
        float S2 = (float)BSZ + g_utxt[i] * g_cA[i];
        g_part[i] = (__logf(S1) - p1) + (__logf(S2) - p2);
    }
}

__global__ void finalize2_kernel(float* __restrict__ out) {
    __shared__ float smr[1024];
    int t = threadIdx.x;
    float s = 0.0f;
    for (int i = t; i < BSZ; i += 1024) s += g_part[i];
    smr[t] = s;
    __syncthreads();
    for (int off = 512; off > 0; off >>= 1) {
        if (t < off) smr[t] += smr[t + off];
        __syncthreads();
    }
    if (t == 0) out[0] = smr[0] * (0.5f / (float)BSZ);
}

// ---------------- launch ----------------
extern "C" void kernel_launch(void* const* d_in, const int* in_sizes, int n_in,
                              void* d_out, int out_size) {
    const float* img    = (const float*)d_in[0];
    const float* txt    = (const float*)d_in[1];
    const int*   labels = (const int*)d_in[2];
    float* out = (float*)d_out;
    (void)in_sizes; (void)n_in; (void)out_size;

    cudaFuncSetAttribute(gemm_exp_kernel, cudaFuncAttributeMaxDynamicSharedMemorySize,
                         GEMM_SMEM_BYTES);

    cvt_kernel<<<(BSZ * DIM + 255) / 256, 256>>>(img, txt);

    dim3 ggrid(BSZ / STRIPC, BSZ / 128);   // (8, 64)
    gemm_exp_kernel<<<ggrid, 256, GEMM_SMEM_BYTES>>>();

    init_kernel<<<BSZ / 256, 256>>>();

    dim3 pgrid(2, BSZ / PR);               // (2, 256)
    for (int it = 0; it < 5; it++) {
        pass_dual<<<pgrid, 256>>>(0);      // rA += K v_img ; cA += K^T v_txt
        upd_u_kernel<<<BSZ / 256, 256>>>();
        pass_dual<<<pgrid, 256>>>(1);      // rB += K u_txt ; cB += K^T u_img
        upd_v_kernel<<<BSZ / 256, 256>>>();
    }

    pass_dual<<<pgrid, 256>>>(0);          // final: rA = K v_img ; cA = K^T v_txt
    finalize1_kernel<<<BSZ / 256, 256>>>(labels);
    finalize2_kernel<<<1, 1024>>>(out);
}

// round 5
// speedup vs baseline: 1.5050x; 1.5050x over previous
#include <cuda_runtime.h>
#include <cuda_fp16.h>
#include <cuda_bf16.h>
#include <cstdint>

#define BSZ 8192
#define DIM 256

// ---------------- device globals ----------------
__device__ __half         g_K[(size_t)BSZ * BSZ];          // 134 MB fp16
__device__ __nv_bfloat16  g_imgb[BSZ * DIM];
__device__ __nv_bfloat16  g_txtb[BSZ * DIM];
__device__ float g_vimg[BSZ], g_vtxt[BSZ], g_uimg[BSZ], g_utxt[BSZ];
__device__ float g_rA[BSZ], g_cA[BSZ], g_rB[BSZ], g_cB[BSZ];
__device__ float g_part[BSZ];

// ---------------- common asm helpers ----------------
__device__ __forceinline__ void cp_async16(uint32_t saddr, const void* gsrc) {
    asm volatile("cp.async.cg.shared.global [%0], [%1], 16;\n" :: "r"(saddr), "l"(gsrc));
}
__device__ __forceinline__ void ldsm4(uint32_t addr, uint32_t& r0, uint32_t& r1,
                                      uint32_t& r2, uint32_t& r3) {
    asm volatile("ldmatrix.sync.aligned.m8n8.x4.shared.b16 {%0,%1,%2,%3}, [%4];"
                 : "=r"(r0), "=r"(r1), "=r"(r2), "=r"(r3) : "r"(addr));
}
__device__ __forceinline__ void ldsm4t(uint32_t addr, uint32_t& r0, uint32_t& r1,
                                       uint32_t& r2, uint32_t& r3) {
    asm volatile("ldmatrix.sync.aligned.m8n8.x4.trans.shared.b16 {%0,%1,%2,%3}, [%4];"
                 : "=r"(r0), "=r"(r1), "=r"(r2), "=r"(r3) : "r"(addr));
}
__device__ __forceinline__ void mma_f16(float c[4], const uint32_t a[4],
                                        uint32_t b0, uint32_t b1) {
    asm volatile(
        "mma.sync.aligned.m16n8k16.row.col.f32.f16.f16.f32 "
        "{%0,%1,%2,%3}, {%4,%5,%6,%7}, {%8,%9}, {%0,%1,%2,%3};\n"
        : "+f"(c[0]), "+f"(c[1]), "+f"(c[2]), "+f"(c[3])
        : "r"(a[0]), "r"(a[1]), "r"(a[2]), "r"(a[3]), "r"(b0), "r"(b1));
}
__device__ __forceinline__ void mma_bf16(float c[4], const uint32_t a[4],
                                         uint32_t b0, uint32_t b1) {
    asm volatile(
        "mma.sync.aligned.m16n8k16.row.col.f32.bf16.bf16.f32 "
        "{%0,%1,%2,%3}, {%4,%5,%6,%7}, {%8,%9}, {%0,%1,%2,%3};\n"
        : "+f"(c[0]), "+f"(c[1]), "+f"(c[2]), "+f"(c[3])
        : "r"(a[0]), "r"(a[1]), "r"(a[2]), "r"(a[3]), "r"(b0), "r"(b1));
}
__device__ __forceinline__ uint32_t swz128(uint32_t off) {   // SW128 byte swizzle
    return off ^ ((off >> 3) & 0x70);
}

// ---------------- fp32 -> bf16 convert ----------------
__global__ void cvt_kernel(const float* __restrict__ img, const float* __restrict__ txt) {
    int i = blockIdx.x * blockDim.x + threadIdx.x;
    if (i < BSZ * DIM) {
        g_imgb[i] = __float2bfloat16_rn(img[i]);
        g_txtb[i] = __float2bfloat16_rn(txt[i]);
    }
}

// ================= GEMM: K = exp(img @ txt^T - 1), fp16 out =================
#define SP 264
#define NB 64
#define STRIPC 1024
#define NTILES (STRIPC / NB)
#define GEMM_SMEM_BYTES ((128 * SP + 2 * NB * SP) * 2)

__global__ __launch_bounds__(256, 1) void gemm_exp_kernel() {
    extern __shared__ __nv_bfloat16 sm[];
    __nv_bfloat16* As = sm;
    __nv_bfloat16* Bs = sm + 128 * SP;
    const uint32_t sAs = (uint32_t)__cvta_generic_to_shared(As);
    const uint32_t sBs = (uint32_t)__cvta_generic_to_shared(Bs);

    const int tid  = threadIdx.x;
    const int lane = tid & 31, warp = tid >> 5;
    const int g = lane >> 2, tq = lane & 3;
    const int wm = warp & 3, wn = warp >> 2;

    const int mTile  = blockIdx.y * 128;
    const int strip0 = blockIdx.x * STRIPC;

    for (int idx = tid; idx < 128 * 32; idx += 256) {
        int r = idx >> 5, c8 = idx & 31;
        *reinterpret_cast<float4*>(As + r * SP + c8 * 8) =
            *reinterpret_cast<const float4*>(g_imgb + (size_t)(mTile + r) * DIM + c8 * 8);
    }
    {
        for (int idx = tid; idx < NB * 32; idx += 256) {
            int r = idx >> 5, c8 = idx & 31;
            uint32_t sa = sBs + (uint32_t)(r * SP + c8 * 8) * 2;
            cp_async16(sa, g_txtb + (size_t)(strip0 + r) * DIM + c8 * 8);
        }
        asm volatile("cp.async.commit_group;\n");
    }

    // per-lane ldmatrix row index pieces
    const int lrow = lane & 15;
    const int lk   = (lane >> 4) * 8;

    for (int bt = 0; bt < NTILES; bt++) {
        if (bt + 1 < NTILES) {
            uint32_t sBd = sBs + (uint32_t)(((bt + 1) & 1) * NB * SP) * 2;
            const int nb0 = strip0 + (bt + 1) * NB;
            for (int idx = tid; idx < NB * 32; idx += 256) {
                int r = idx >> 5, c8 = idx & 31;
                cp_async16(sBd + (uint32_t)(r * SP + c8 * 8) * 2,
                           g_txtb + (size_t)(nb0 + r) * DIM + c8 * 8);
            }
            asm volatile("cp.async.commit_group;\n");
            asm volatile("cp.async.wait_group 1;\n");
        } else {
            asm volatile("cp.async.wait_group 0;\n");
        }
        __syncthreads();

        const uint32_t sBb = sBs + (uint32_t)((bt & 1) * NB * SP) * 2;
        float c[2][4][4];
        #pragma unroll
        for (int mi = 0; mi < 2; mi++)
            #pragma unroll
            for (int ni = 0; ni < 4; ni++)
                #pragma unroll
                for (int k = 0; k < 4; k++) c[mi][ni][k] = 0.0f;

        #pragma unroll
        for (int ks = 0; ks < 16; ks++) {
            const int k0 = ks * 16;
            uint32_t a[2][4], b[4][2];
            #pragma unroll
            for (int mi = 0; mi < 2; mi++) {
                int rb = wm * 32 + mi * 16;
                uint32_t addr = sAs + (uint32_t)((rb + lrow) * SP + k0 + lk) * 2;
                ldsm4(addr, a[mi][0], a[mi][1], a[mi][2], a[mi][3]);
            }
            #pragma unroll
            for (int g16 = 0; g16 < 2; g16++) {
                int nb = wn * 32 + g16 * 16;
                uint32_t q0, q1, q2, q3;
                uint32_t addr = sBb + (uint32_t)((nb + lrow) * SP + k0 + lk) * 2;
                ldsm4(addr, q0, q1, q2, q3);
                b[g16 * 2][0] = q0;     b[g16 * 2][1] = q2;
                b[g16 * 2 + 1][0] = q1; b[g16 * 2 + 1][1] = q3;
            }
            #pragma unroll
            for (int mi = 0; mi < 2; mi++)
                #pragma unroll
                for (int ni = 0; ni < 4; ni++)
                    mma_bf16(c[mi][ni], a[mi], b[ni][0], b[ni][1]);
        }

        const int nTile = strip0 + bt * NB;
        #pragma unroll
        for (int mi = 0; mi < 2; mi++) {
            #pragma unroll
            for (int ni = 0; ni < 4; ni++) {
                int row0 = mTile + wm * 32 + mi * 16 + g;
                int col  = nTile + wn * 32 + ni * 8 + 2 * tq;
                __half2 h01 = __floats2half2_rn(__expf(c[mi][ni][0] - 1.0f), __expf(c[mi][ni][1] - 1.0f));
                __half2 h23 = __floats2half2_rn(__expf(c[mi][ni][2] - 1.0f), __expf(c[mi][ni][3] - 1.0f));
                *reinterpret_cast<__half2*>(g_K + (size_t)row0 * BSZ + col)       = h01;
                *reinterpret_cast<__half2*>(g_K + (size_t)(row0 + 8) * BSZ + col) = h23;
            }
        }
        __syncthreads();
    }
}

// ---------------- init ----------------
__global__ void init_kernel() {
    int i = blockIdx.x * blockDim.x + threadIdx.x;
    if (i < BSZ) {
        g_vimg[i] = 1.0f; g_vtxt[i] = 1.0f;
        g_rA[i] = 0.0f; g_cA[i] = 0.0f; g_rB[i] = 0.0f; g_cB[i] = 0.0f;
    }
}

// ============== tensor-core dual pass ==============
// Block tile: 128 rows x 2048 cols, streamed in 128x64 chunks via cp.async (3 stages).
// row-dir: y1[r] += sum_c K[r][c] * x1[c]   (ldmatrix,  A = K tile)
// col-dir: y2[c] += sum_r K[r][c] * x2[r]   (ldmatrix.trans, A = K^T tile)
// mode 0: x1=v_img, x2=v_txt, y1=rA, y2=cA
// mode 1: x1=1/cA (u_txt), x2=1/rA (u_img), y1=rB, y2=cB
#define RB 128
#define CS 2048
#define CKC 64
#define NCHUNK (CS / CKC)          // 32
#define TILE_BYTES (RB * CKC * 2)  // 16384
#define PASS_SMEM (3 * TILE_BYTES + (CS / 2) * 4 + (RB / 2) * 4)

__global__ __launch_bounds__(256) void pass_tensor(int mode) {
    extern __shared__ char smraw[];
    uint32_t* x1p = reinterpret_cast<uint32_t*>(smraw + 3 * TILE_BYTES);       // 1024 half2
    uint32_t* x2p = reinterpret_cast<uint32_t*>(smraw + 3 * TILE_BYTES + (CS / 2) * 4); // 64 half2
    const uint32_t stile = (uint32_t)__cvta_generic_to_shared(smraw);

    const int t = threadIdx.x, lane = t & 31, w = t >> 5;
    const int colbase = blockIdx.x * CS;
    const int r0 = blockIdx.y * RB;

    float* y1 = (mode == 0) ? g_rA : g_rB;
    float* y2 = (mode == 0) ? g_cA : g_cB;

    // ---- issue chunk 0 and 1 ----
    #pragma unroll
    for (int ck = 0; ck < 2; ck++) {
        #pragma unroll
        for (int j = 0; j < 4; j++) {
            int u = t + 256 * j;
            int row = u >> 3, c16 = u & 7;
            uint32_t off = swz128((uint32_t)(row * 128 + c16 * 16));
            cp_async16(stile + ck * TILE_BYTES + off,
                       g_K + (size_t)(r0 + row) * BSZ + colbase + ck * CKC + c16 * 8);
        }
        asm volatile("cp.async.commit_group;\n");
    }

    // ---- x vectors ----
    if (mode == 0) {
        for (int i = t; i < CS / 2; i += 256) {
            int c = colbase + 2 * i;
            __half2 h = __floats2half2_rn(g_vimg[c], g_vimg[c + 1]);
            x1p[i] = *reinterpret_cast<uint32_t*>(&h);
        }
        if (t < RB / 2) {
            int r = r0 + 2 * t;
            __half2 h = __floats2half2_rn(g_vtxt[r], g_vtxt[r + 1]);
            x2p[t] = *reinterpret_cast<uint32_t*>(&h);
        }
    } else {
        for (int i = t; i < CS / 2; i += 256) {
            int c = colbase + 2 * i;
            __half2 h = __floats2half2_rn(1.0f / g_cA[c], 1.0f / g_cA[c + 1]);
            x1p[i] = *reinterpret_cast<uint32_t*>(&h);
        }
        if (t < RB / 2) {
            int r = r0 + 2 * t;
            __half2 h = __floats2half2_rn(1.0f / g_rA[r], 1.0f / g_rA[r + 1]);
            x2p[t] = *reinterpret_cast<uint32_t*>(&h);
        }
    }
    __syncthreads();

    // per-lane ldmatrix offsets (bytes, pre-swizzle)
    const uint32_t rowoff_r = (uint32_t)((16 * w + (lane & 15)) * 128 + (lane >> 4) * 16);
    const int rowc = (lane & 7) + ((lane >> 4) << 3);
    const uint32_t coloffc = (uint32_t)((w & 3) * 32 + ((lane >> 3) & 1) * 16);
    const int rbase = (w >> 2) * 64;

    float dr[4] = {0.f, 0.f, 0.f, 0.f};

    for (int i = 0; i < NCHUNK; i++) {
        if (i < NCHUNK - 1) { asm volatile("cp.async.wait_group 1;\n"); }
        else                { asm volatile("cp.async.wait_group 0;\n"); }
        __syncthreads();

        if (i + 2 < NCHUNK) {
            const int ck = i + 2;
            const uint32_t sb = stile + (uint32_t)((ck % 3) * TILE_BYTES);
            #pragma unroll
            for (int j = 0; j < 4; j++) {
                int u = t + 256 * j;
                int row = u >> 3, c16 = u & 7;
                uint32_t off = swz128((uint32_t)(row * 128 + c16 * 16));
                cp_async16(sb + off,
                           g_K + (size_t)(r0 + row) * BSZ + colbase + ck * CKC + c16 * 8);
            }
            asm volatile("cp.async.commit_group;\n");
        }

        const uint32_t base = stile + (uint32_t)((i % 3) * TILE_BYTES);

        // ---- col-dir: 16 cols (w&3), 4 row-steps of 16 ----
        float dc[4] = {0.f, 0.f, 0.f, 0.f};
        #pragma unroll
        for (int p = 0; p < 4; p++) {
            uint32_t a[4];
            uint32_t off = (uint32_t)((rbase + 16 * p + rowc) * 128) + coloffc;
            ldsm4t(base + swz128(off), a[0], a[1], a[2], a[3]);
            uint32_t b0 = x2p[(rbase >> 1) + 8 * p + (lane & 3)];
            uint32_t b1 = x2p[(rbase >> 1) + 8 * p + (lane & 3) + 4];
            mma_f16(dc, a, b0, b1);
        }
        if ((lane & 3) == 0) {
            int cc = colbase + i * CKC + (w & 3) * 16 + (lane >> 2);
            atomicAdd(&y2[cc], dc[0]);
            atomicAdd(&y2[cc + 8], dc[2]);
        }

        // ---- row-dir: 16 rows (w), 4 col-subtiles of 16 ----
        #pragma unroll
        for (int s = 0; s < 4; s++) {
            uint32_t a[4];
            uint32_t off = rowoff_r + (uint32_t)(s * 32);
            ldsm4(base + swz128(off), a[0], a[1], a[2], a[3]);
            uint32_t b0 = x1p[i * 32 + 8 * s + (lane & 3)];
            uint32_t b1 = x1p[i * 32 + 8 * s + (lane & 3) + 4];
            mma_f16(dr, a, b0, b1);
        }
    }

    if ((lane & 3) == 0) {
        int rr = r0 + 16 * w + (lane >> 2);
        atomicAdd(&y1[rr], dr[0]);
        atomicAdd(&y1[rr + 8], dr[2]);
    }
}

// ---------------- per-iteration scalar update (u store + v clamp + zero) ----------------
__global__ void upd_uv_kernel() {
    int i = blockIdx.x * blockDim.x + threadIdx.x;
    if (i < BSZ) {
        g_uimg[i] = 1.0f / g_rA[i];
        g_utxt[i] = 1.0f / g_cA[i];

        float tt = g_vimg[i] * g_cB[i];
        float f1 = fmaxf(0.5f / tt, 1.0f);
        tt *= f1;
        float f2 = fminf(4.5f / tt, 1.0f);
        g_vimg[i] *= f1 * f2;

        float tu = g_vtxt[i] * g_rB[i];
        float h1 = fmaxf(0.5f / tu, 1.0f);
        tu *= h1;
        float h2 = fminf(4.5f / tu, 1.0f);
        g_vtxt[i] *= h1 * h2;

        g_rA[i] = 0.0f; g_cA[i] = 0.0f; g_rB[i] = 0.0f; g_cB[i] = 0.0f;
    }
}

// ---------------- finalize ----------------
__global__ void finalize1_kernel(const int* __restrict__ labels) {
    int i = blockIdx.x * blockDim.x + threadIdx.x;
    if (i < BSZ) {
        int l = labels[i];
        float p1 = g_uimg[i] * __half2float(g_K[(size_t)i * BSZ + l]) * g_vimg[l];
        float p2 = g_utxt[i] * __half2float(g_K[(size_t)l * BSZ + i]) * g_vtxt[l];
        float S1 = (float)BSZ + g_uimg[i] * g_rA[i];
        float S2 = (float)BSZ + g_utxt[i] * g_cA[i];
        g_part[i] = (__logf(S1) - p1) + (__logf(S2) - p2);
    }
}

__global__ void finalize2_kernel(float* __restrict__ out) {
    __shared__ float smr[1024];
    int t = threadIdx.x;
    float s = 0.0f;
    for (int i = t; i < BSZ; i += 1024) s += g_part[i];
    smr[t] = s;
    __syncthreads();
    for (int off = 512; off > 0; off >>= 1) {
        if (t < off) smr[t] += smr[t + off];
        __syncthreads();
    }
    if (t == 0) out[0] = smr[0] * (0.5f / (float)BSZ);
}

// ---------------- launch ----------------
extern "C" void kernel_launch(void* const* d_in, const int* in_sizes, int n_in,
                              void* d_out, int out_size) {
    const float* img    = (const float*)d_in[0];
    const float* txt    = (const float*)d_in[1];
    const int*   labels = (const int*)d_in[2];
    float* out = (float*)d_out;
    (void)in_sizes; (void)n_in; (void)out_size;

    cudaFuncSetAttribute(gemm_exp_kernel, cudaFuncAttributeMaxDynamicSharedMemorySize,
                         GEMM_SMEM_BYTES);
    cudaFuncSetAttribute(pass_tensor, cudaFuncAttributeMaxDynamicSharedMemorySize,
                         PASS_SMEM);

    cvt_kernel<<<(BSZ * DIM + 255) / 256, 256>>>(img, txt);

    dim3 ggrid(BSZ / STRIPC, BSZ / 128);   // (8, 64)
    gemm_exp_kernel<<<ggrid, 256, GEMM_SMEM_BYTES>>>();

    init_kernel<<<BSZ / 256, 256>>>();

    dim3 pgrid(BSZ / CS, BSZ / RB);        // (4, 64)
    for (int it = 0; it < 5; it++) {
        pass_tensor<<<pgrid, 256, PASS_SMEM>>>(0);  // rA = K v_img ; cA = K^T v_txt
        pass_tensor<<<pgrid, 256, PASS_SMEM>>>(1);  // rB = K u_txt ; cB = K^T u_img (u derived in-kernel)
        upd_uv_kernel<<<BSZ / 256, 256>>>();        // store u, clamp v, zero sums
    }

    pass_tensor<<<pgrid, 256, PASS_SMEM>>>(0);      // final: rA = K v_img ; cA = K^T v_txt
    finalize1_kernel<<<BSZ / 256, 256>>>(labels);
    finalize2_kernel<<<1, 1024>>>(out);
}

// round 6
// speedup vs baseline: 1.5834x; 1.0521x over previous
#include <cuda_runtime.h>
#include <cuda_fp16.h>
#include <cuda_bf16.h>
#include <cstdint>

#define BSZ 8192
#define DIM 256

// ---------------- device globals ----------------
__device__ __half   g_K[(size_t)BSZ * BSZ];          // 134 MB fp16
__device__ uint8_t  g_img8[BSZ * DIM];
__device__ uint8_t  g_txt8[BSZ * DIM];
__device__ float g_vimg[BSZ], g_vtxt[BSZ], g_uimg[BSZ], g_utxt[BSZ];
__device__ float g_rA[BSZ], g_cA[BSZ], g_rB[BSZ], g_cB[BSZ];
__device__ float g_part[BSZ];

// ---------------- asm helpers ----------------
__device__ __forceinline__ void cp_async16(uint32_t saddr, const void* gsrc) {
    asm volatile("cp.async.cg.shared.global [%0], [%1], 16;\n" :: "r"(saddr), "l"(gsrc));
}
__device__ __forceinline__ void ldsm4(uint32_t addr, uint32_t& r0, uint32_t& r1,
                                      uint32_t& r2, uint32_t& r3) {
    asm volatile("ldmatrix.sync.aligned.m8n8.x4.shared.b16 {%0,%1,%2,%3}, [%4];"
                 : "=r"(r0), "=r"(r1), "=r"(r2), "=r"(r3) : "r"(addr));
}
__device__ __forceinline__ void ldsm4t(uint32_t addr, uint32_t& r0, uint32_t& r1,
                                       uint32_t& r2, uint32_t& r3) {
    asm volatile("ldmatrix.sync.aligned.m8n8.x4.trans.shared.b16 {%0,%1,%2,%3}, [%4];"
                 : "=r"(r0), "=r"(r1), "=r"(r2), "=r"(r3) : "r"(addr));
}
__device__ __forceinline__ void mma_f16(float c[4], const uint32_t a[4],
                                        uint32_t b0, uint32_t b1) {
    asm volatile(
        "mma.sync.aligned.m16n8k16.row.col.f32.f16.f16.f32 "
        "{%0,%1,%2,%3}, {%4,%5,%6,%7}, {%8,%9}, {%0,%1,%2,%3};\n"
        : "+f"(c[0]), "+f"(c[1]), "+f"(c[2]), "+f"(c[3])
        : "r"(a[0]), "r"(a[1]), "r"(a[2]), "r"(a[3]), "r"(b0), "r"(b1));
}
__device__ __forceinline__ void mma_fp8(float c[4], const uint32_t a[4],
                                        uint32_t b0, uint32_t b1) {
    asm volatile(
        "mma.sync.aligned.m16n8k32.row.col.f32.e4m3.e4m3.f32 "
        "{%0,%1,%2,%3}, {%4,%5,%6,%7}, {%8,%9}, {%0,%1,%2,%3};\n"
        : "+f"(c[0]), "+f"(c[1]), "+f"(c[2]), "+f"(c[3])
        : "r"(a[0]), "r"(a[1]), "r"(a[2]), "r"(a[3]), "r"(b0), "r"(b1));
}
__device__ __forceinline__ unsigned short pack_e4m3(float hi, float lo) {
    unsigned short r;  // d[7:0]=cvt(lo), d[15:8]=cvt(hi)
    asm("cvt.rn.satfinite.e4m3x2.f32 %0, %1, %2;" : "=h"(r) : "f"(hi), "f"(lo));
    return r;
}
__device__ __forceinline__ uint32_t swz128(uint32_t off) {
    return off ^ ((off >> 3) & 0x70);
}

// ---------------- fp32 -> e4m3 convert ----------------
__global__ void cvt8_kernel(const float* __restrict__ img, const float* __restrict__ txt) {
    int i = blockIdx.x * blockDim.x + threadIdx.x;
    if (i < BSZ * DIM / 2) {
        reinterpret_cast<unsigned short*>(g_img8)[i] = pack_e4m3(img[2 * i + 1], img[2 * i]);
        reinterpret_cast<unsigned short*>(g_txt8)[i] = pack_e4m3(txt[2 * i + 1], txt[2 * i]);
    }
}

// ================= GEMM: K = exp(img @ txt^T - 1), fp8 in, fp16 out =================
#define SP8 272                 // bytes per smem row (256 data + 16 pad) -> conflict-free
#define NB 64
#define STRIPC 1024
#define NTILES (STRIPC / NB)
#define GEMM_SMEM_BYTES ((128 + 2 * NB) * SP8)

__global__ __launch_bounds__(256, 1) void gemm_exp_kernel() {
    extern __shared__ uint8_t sm8[];
    uint8_t* As = sm8;
    uint8_t* Bs = sm8 + 128 * SP8;
    const uint32_t sAs = (uint32_t)__cvta_generic_to_shared(As);
    const uint32_t sBs = (uint32_t)__cvta_generic_to_shared(Bs);

    const int tid  = threadIdx.x;
    const int lane = tid & 31, warp = tid >> 5;
    const int g = lane >> 2, tq = lane & 3;
    const int wm = warp & 3, wn = warp >> 2;

    const int mTile  = blockIdx.y * 128;
    const int strip0 = blockIdx.x * STRIPC;

    // A tile: 128 rows x 256 B
    for (int idx = tid; idx < 128 * 16; idx += 256) {
        int r = idx >> 4, c16 = idx & 15;
        *reinterpret_cast<uint4*>(As + r * SP8 + c16 * 16) =
            *reinterpret_cast<const uint4*>(g_img8 + (size_t)(mTile + r) * DIM + c16 * 16);
    }
    // prefetch B tile 0
    for (int idx = tid; idx < NB * 16; idx += 256) {
        int r = idx >> 4, c16 = idx & 15;
        cp_async16(sBs + (uint32_t)(r * SP8 + c16 * 16),
                   g_txt8 + (size_t)(strip0 + r) * DIM + c16 * 16);
    }
    asm volatile("cp.async.commit_group;\n");

    const int lrow = lane & 15;
    const int lkB  = (lane >> 4) * 16;   // byte offset within 32B k-chunk

    for (int bt = 0; bt < NTILES; bt++) {
        if (bt + 1 < NTILES) {
            uint32_t sBd = sBs + (uint32_t)(((bt + 1) & 1) * NB * SP8);
            const int nb0 = strip0 + (bt + 1) * NB;
            for (int idx = tid; idx < NB * 16; idx += 256) {
                int r = idx >> 4, c16 = idx & 15;
                cp_async16(sBd + (uint32_t)(r * SP8 + c16 * 16),
                           g_txt8 + (size_t)(nb0 + r) * DIM + c16 * 16);
            }
            asm volatile("cp.async.commit_group;\n");
            asm volatile("cp.async.wait_group 1;\n");
        } else {
            asm volatile("cp.async.wait_group 0;\n");
        }
        __syncthreads();

        const uint32_t sBb = sBs + (uint32_t)((bt & 1) * NB * SP8);
        float c[2][4][4];
        #pragma unroll
        for (int mi = 0; mi < 2; mi++)
            #pragma unroll
            for (int ni = 0; ni < 4; ni++)
                #pragma unroll
                for (int k = 0; k < 4; k++) c[mi][ni][k] = 0.0f;

        #pragma unroll
        for (int ks = 0; ks < 8; ks++) {
            const int k0B = ks * 32;
            uint32_t a[2][4], b[4][2];
            #pragma unroll
            for (int mi = 0; mi < 2; mi++) {
                int rb = wm * 32 + mi * 16;
                uint32_t addr = sAs + (uint32_t)((rb + lrow) * SP8 + k0B + lkB);
                ldsm4(addr, a[mi][0], a[mi][1], a[mi][2], a[mi][3]);
            }
            #pragma unroll
            for (int g16 = 0; g16 < 2; g16++) {
                int nb = wn * 32 + g16 * 16;
                uint32_t q0, q1, q2, q3;
                uint32_t addr = sBb + (uint32_t)((nb + lrow) * SP8 + k0B + lkB);
                ldsm4(addr, q0, q1, q2, q3);
                b[g16 * 2][0] = q0;     b[g16 * 2][1] = q2;
                b[g16 * 2 + 1][0] = q1; b[g16 * 2 + 1][1] = q3;
            }
            #pragma unroll
            for (int mi = 0; mi < 2; mi++)
                #pragma unroll
                for (int ni = 0; ni < 4; ni++)
                    mma_fp8(c[mi][ni], a[mi], b[ni][0], b[ni][1]);
        }

        const int nTile = strip0 + bt * NB;
        #pragma unroll
        for (int mi = 0; mi < 2; mi++) {
            #pragma unroll
            for (int ni = 0; ni < 4; ni++) {
                int row0 = mTile + wm * 32 + mi * 16 + g;
                int col  = nTile + wn * 32 + ni * 8 + 2 * tq;
                __half2 h01 = __floats2half2_rn(__expf(c[mi][ni][0] - 1.0f), __expf(c[mi][ni][1] - 1.0f));
                __half2 h23 = __floats2half2_rn(__expf(c[mi][ni][2] - 1.0f), __expf(c[mi][ni][3] - 1.0f));
                *reinterpret_cast<__half2*>(g_K + (size_t)row0 * BSZ + col)       = h01;
                *reinterpret_cast<__half2*>(g_K + (size_t)(row0 + 8) * BSZ + col) = h23;
            }
        }
        __syncthreads();
    }
}

// ---------------- init ----------------
__global__ void init_kernel() {
    int i = blockIdx.x * blockDim.x + threadIdx.x;
    if (i < BSZ) {
        g_vimg[i] = 1.0f; g_vtxt[i] = 1.0f;
        g_rA[i] = 0.0f; g_cA[i] = 0.0f; g_rB[i] = 0.0f; g_cB[i] = 0.0f;
    }
}

// ============== tensor-core dual pass ==============
// Block tile: 128 rows x 1024 cols, streamed in 128x64 chunks via cp.async (3 stages).
#define RB 128
#define CS 1024
#define CKC 64
#define NCHUNK (CS / CKC)          // 16
#define TILE_BYTES (RB * CKC * 2)  // 16384
#define PASS_SMEM (3 * TILE_BYTES + (CS / 2) * 4 + (RB / 2) * 4)

__global__ __launch_bounds__(256) void pass_tensor(int mode) {
    extern __shared__ char smraw[];
    uint32_t* x1p = reinterpret_cast<uint32_t*>(smraw + 3 * TILE_BYTES);
    uint32_t* x2p = reinterpret_cast<uint32_t*>(smraw + 3 * TILE_BYTES + (CS / 2) * 4);
    const uint32_t stile = (uint32_t)__cvta_generic_to_shared(smraw);

    const int t = threadIdx.x, lane = t & 31, w = t >> 5;
    const int colbase = blockIdx.x * CS;
    const int r0 = blockIdx.y * RB;

    float* y1 = (mode == 0) ? g_rA : g_rB;
    float* y2 = (mode == 0) ? g_cA : g_cB;

    #pragma unroll
    for (int ck = 0; ck < 2; ck++) {
        #pragma unroll
        for (int j = 0; j < 4; j++) {
            int u = t + 256 * j;
            int row = u >> 3, c16 = u & 7;
            uint32_t off = swz128((uint32_t)(row * 128 + c16 * 16));
            cp_async16(stile + ck * TILE_BYTES + off,
                       g_K + (size_t)(r0 + row) * BSZ + colbase + ck * CKC + c16 * 8);
        }
        asm volatile("cp.async.commit_group;\n");
    }

    if (mode == 0) {
        for (int i = t; i < CS / 2; i += 256) {
            int c = colbase + 2 * i;
            __half2 h = __floats2half2_rn(g_vimg[c], g_vimg[c + 1]);
            x1p[i] = *reinterpret_cast<uint32_t*>(&h);
        }
        if (t < RB / 2) {
            int r = r0 + 2 * t;
            __half2 h = __floats2half2_rn(g_vtxt[r], g_vtxt[r + 1]);
            x2p[t] = *reinterpret_cast<uint32_t*>(&h);
        }
    } else {
        for (int i = t; i < CS / 2; i += 256) {
            int c = colbase + 2 * i;
            __half2 h = __floats2half2_rn(1.0f / g_cA[c], 1.0f / g_cA[c + 1]);
            x1p[i] = *reinterpret_cast<uint32_t*>(&h);
        }
        if (t < RB / 2) {
            int r = r0 + 2 * t;
            __half2 h = __floats2half2_rn(1.0f / g_rA[r], 1.0f / g_rA[r + 1]);
            x2p[t] = *reinterpret_cast<uint32_t*>(&h);
        }
    }
    __syncthreads();

    const uint32_t rowoff_r = (uint32_t)((16 * w + (lane & 15)) * 128 + (lane >> 4) * 16);
    const int rowc = (lane & 7) + ((lane >> 4) << 3);
    const uint32_t coloffc = (uint32_t)((w & 3) * 32 + ((lane >> 3) & 1) * 16);
    const int rbase = (w >> 2) * 64;

    float dr[4] = {0.f, 0.f, 0.f, 0.f};

    for (int i = 0; i < NCHUNK; i++) {
        if (i < NCHUNK - 1) { asm volatile("cp.async.wait_group 1;\n"); }
        else                { asm volatile("cp.async.wait_group 0;\n"); }
        __syncthreads();

        if (i + 2 < NCHUNK) {
            const int ck = i + 2;
            const uint32_t sb = stile + (uint32_t)((ck % 3) * TILE_BYTES);
            #pragma unroll
            for (int j = 0; j < 4; j++) {
                int u = t + 256 * j;
                int row = u >> 3, c16 = u & 7;
                uint32_t off = swz128((uint32_t)(row * 128 + c16 * 16));
                cp_async16(sb + off,
                           g_K + (size_t)(r0 + row) * BSZ + colbase + ck * CKC + c16 * 8);
            }
            asm volatile("cp.async.commit_group;\n");
        }

        const uint32_t base = stile + (uint32_t)((i % 3) * TILE_BYTES);

        float dc[4] = {0.f, 0.f, 0.f, 0.f};
        #pragma unroll
        for (int p = 0; p < 4; p++) {
            uint32_t a[4];
            uint32_t off = (uint32_t)((rbase + 16 * p + rowc) * 128) + coloffc;
            ldsm4t(base + swz128(off), a[0], a[1], a[2], a[3]);
            uint32_t b0 = x2p[(rbase >> 1) + 8 * p + (lane & 3)];
            uint32_t b1 = x2p[(rbase >> 1) + 8 * p + (lane & 3) + 4];
            mma_f16(dc, a, b0, b1);
        }
        if ((lane & 3) == 0) {
            int cc = colbase + i * CKC + (w & 3) * 16 + (lane >> 2);
            atomicAdd(&y2[cc], dc[0]);
            atomicAdd(&y2[cc + 8], dc[2]);
        }

        #pragma unroll
        for (int s = 0; s < 4; s++) {
            uint32_t a[4];
            uint32_t off = rowoff_r + (uint32_t)(s * 32);
            ldsm4(base + swz128(off), a[0], a[1], a[2], a[3]);
            uint32_t b0 = x1p[i * 32 + 8 * s + (lane & 3)];
            uint32_t b1 = x1p[i * 32 + 8 * s + (lane & 3) + 4];
            mma_f16(dr, a, b0, b1);
        }
    }

    if ((lane & 3) == 0) {
        int rr = r0 + 16 * w + (lane >> 2);
        atomicAdd(&y1[rr], dr[0]);
        atomicAdd(&y1[rr + 8], dr[2]);
    }
}

// ---------------- per-iteration scalar update ----------------
__global__ void upd_uv_kernel() {
    int i = blockIdx.x * blockDim.x + threadIdx.x;
    if (i < BSZ) {
        g_uimg[i] = 1.0f / g_rA[i];
        g_utxt[i] = 1.0f / g_cA[i];

        float tt = g_vimg[i] * g_cB[i];
        float f1 = fmaxf(0.5f / tt, 1.0f);
        tt *= f1;
        float f2 = fminf(4.5f / tt, 1.0f);
        g_vimg[i] *= f1 * f2;

        float tu = g_vtxt[i] * g_rB[i];
        float h1 = fmaxf(0.5f / tu, 1.0f);
        tu *= h1;
        float h2 = fminf(4.5f / tu, 1.0f);
        g_vtxt[i] *= h1 * h2;

        g_rA[i] = 0.0f; g_cA[i] = 0.0f; g_rB[i] = 0.0f; g_cB[i] = 0.0f;
    }
}

// ---------------- finalize ----------------
__global__ void finalize1_kernel(const int* __restrict__ labels) {
    int i = blockIdx.x * blockDim.x + threadIdx.x;
    if (i < BSZ) {
        int l = labels[i];
        float p1 = g_uimg[i] * __half2float(g_K[(size_t)i * BSZ + l]) * g_vimg[l];
        float p2 = g_utxt[i] * __half2float(g_K[(size_t)l * BSZ + i]) * g_vtxt[l];
        float S1 = (float)BSZ + g_uimg[i] * g_rA[i];
        float S2 = (float)BSZ + g_utxt[i] * g_cA[i];
        g_part[i] = (__logf(S1) - p1) + (__logf(S2) - p2);
    }
}

__global__ void finalize2_kernel(float* __restrict__ out) {
    __shared__ float smr[1024];
    int t = threadIdx.x;
    float s = 0.0f;
    for (int i = t; i < BSZ; i += 1024) s += g_part[i];
    smr[t] = s;
    __syncthreads();
    for (int off = 512; off > 0; off >>= 1) {
        if (t < off) smr[t] += smr[t + off];
        __syncthreads();
    }
    if (t == 0) out[0] = smr[0] * (0.5f / (float)BSZ);
}

// ---------------- launch ----------------
extern "C" void kernel_launch(void* const* d_in, const int* in_sizes, int n_in,
                              void* d_out, int out_size) {
    const float* img    = (const float*)d_in[0];
    const float* txt    = (const float*)d_in[1];
    const int*   labels = (const int*)d_in[2];
    float* out = (float*)d_out;
    (void)in_sizes; (void)n_in; (void)out_size;

    cudaFuncSetAttribute(gemm_exp_kernel, cudaFuncAttributeMaxDynamicSharedMemorySize,
                         GEMM_SMEM_BYTES);
    cudaFuncSetAttribute(pass_tensor, cudaFuncAttributeMaxDynamicSharedMemorySize,
                         PASS_SMEM);

    cvt8_kernel<<<(BSZ * DIM / 2 + 255) / 256, 256>>>(img, txt);

    dim3 ggrid(BSZ / STRIPC, BSZ / 128);   // (8, 64)
    gemm_exp_kernel<<<ggrid, 256, GEMM_SMEM_BYTES>>>();

    init_kernel<<<BSZ / 256, 256>>>();

    dim3 pgrid(BSZ / CS, BSZ / RB);        // (8, 64) = 512 blocks
    for (int it = 0; it < 5; it++) {
        pass_tensor<<<pgrid, 256, PASS_SMEM>>>(0);
        pass_tensor<<<pgrid, 256, PASS_SMEM>>>(1);
        upd_uv_kernel<<<BSZ / 256, 256>>>();
    }

    pass_tensor<<<pgrid, 256, PASS_SMEM>>>(0);
    finalize1_kernel<<<BSZ / 256, 256>>>(labels);
    finalize2_kernel<<<1, 1024>>>(out);
}